// round 6
// baseline (speedup 1.0000x reference)
#include <cuda_runtime.h>
#include <math.h>

#define CIN 64
#define COUT_PER 32
#define LALPHA 0.2f

typedef unsigned long long u64;

__device__ __forceinline__ u64 pk2(float v) {
    u64 r; asm("mov.b64 %0, {%1, %1};" : "=l"(r) : "f"(v)); return r;
}
__device__ __forceinline__ u64 pk(float lo, float hi) {
    u64 r; asm("mov.b64 %0, {%1, %2};" : "=l"(r) : "f"(lo), "f"(hi)); return r;
}
__device__ __forceinline__ void fma2(u64& d, u64 a, u64 b) {
    asm("fma.rn.f32x2 %0, %1, %2, %0;" : "+l"(d) : "l"(a), "l"(b));
}
__device__ __forceinline__ float2 up(u64 v) {
    float2 f; asm("mov.b64 {%0, %1}, %2;" : "=f"(f.x), "=f"(f.y) : "l"(v)); return f;
}
__device__ __forceinline__ float lk(float v) { return v > 0.f ? v : LALPHA * v; }

// ---------------- static device scratch ----------------
// D (forward DFT [r][t]) / C (inverse DFT [t][j]); offs: fft32->0, fft64->1088, fft128->5312
__device__ float g_D[21952];
__device__ float g_C[21952];
// G[k][j=ri*64+c][o2=2o+rio]; offs 0 / 139264 / 409600
__device__ float g_G[942080];
// X[k][f][ri][c]; offs 0 / 4456448 / 8781824
__device__ float g_X[13041664];
// Z[f][j=2k+ri][o]; offs 0 / 2228224 / 4390912
__device__ float g_Z[6520832];

// ---------------- precompute ----------------
__global__ void k_build_dft() {
    int ffti = blockIdx.y;
    int N = 32 << ffti;
    int bins = N / 2 + 1;
    int R = 2 * bins;
    int total = R * N;
    int off = (ffti == 0) ? 0 : (ffti == 1 ? 1088 : 5312);
    int stride = gridDim.x * blockDim.x;
    for (int idx = blockIdx.x * blockDim.x + threadIdx.x; idx < total; idx += stride) {
        {   // D [r][t]
            int r = idx / N, t = idx % N;
            int k = r >> 1, ri = r & 1;
            int m = (k * t) % N;
            float s, c;
            sincospif(2.0f * (float)m / (float)N, &s, &c);
            g_D[off + idx] = ri ? -s : c;
        }
        {   // C [t][j]
            int t = idx / R, j = idx % R;
            int k = j >> 1, ri = j & 1;
            int m = (k * t) % N;
            float s, c;
            sincospif(2.0f * (float)m / (float)N, &s, &c);
            float w = (k == 0 || k == bins - 1) ? 1.0f : 2.0f;
            g_C[off + idx] = (ri ? -s : c) * (w / (float)N);
        }
    }
}

__global__ void k_build_G(const float* __restrict__ kr, const float* __restrict__ ki) {
    int ffti = blockIdx.y;
    int N = 32 << ffti;
    int bins = N / 2 + 1;
    int goff = (ffti == 0) ? 0 : (ffti == 1 ? 139264 : 409600);
    int total = bins * CIN * COUT_PER;
    int stride = gridDim.x * blockDim.x;
    for (int idx = blockIdx.x * blockDim.x + threadIdx.x; idx < total; idx += stride) {
        int k = idx / (CIN * COUT_PER);
        int rem = idx % (CIN * COUT_PER);
        int c = rem / COUT_PER, o = rem % COUT_PER;
        float vr, vi;
        if (bins == 33) {
            vr = kr[k * 2048 + rem];
            vi = ki[k * 2048 + rem];
        } else {
            float src = (k + 0.5f) * (33.0f / (float)bins) - 0.5f;
            float fl = floorf(src);
            int i0 = (int)fl;
            float f = src - fl;
            int i0c = i0 < 0 ? 0 : i0;
            int i1c = i0 + 1 > 32 ? 32 : i0 + 1;
            vr = (1.0f - f) * kr[i0c * 2048 + rem] + f * kr[i1c * 2048 + rem];
            vi = (1.0f - f) * ki[i0c * 2048 + rem] + f * ki[i1c * 2048 + rem];
        }
        float* Gk = g_G + goff + k * 8192;
        Gk[c * 64 + 2 * o]            = vr;
        Gk[c * 64 + 2 * o + 1]        = vi;
        Gk[(64 + c) * 64 + 2 * o]     = -vi;
        Gk[(64 + c) * 64 + 2 * o + 1] = vr;
    }
}

// ---------------- stage 1: forward DFT (one frame per CTA) ----------------
// D rows 1 and N+1 are identically zero -> compute exactly N rows (0,2..N).
template <int N, int DOFF, int XOFF, int F>
__global__ void k_stage1(const float* __restrict__ x) {
    constexpr int RT = (N + 31) / 32;
    extern __shared__ float sm[];
    float* D_s = sm;                 // N x (N+1), remapped rows
    float* x_s = sm + N * (N + 1);   // N x 64
    const int tid = threadIdx.x;
    const int f = blockIdx.x;

    for (int idx = tid; idx < N * N; idx += 256) {
        int rp = idx / N, t = idx % N;
        int ra = rp + (rp > 0);
        D_s[rp * (N + 1) + t] = g_D[DOFF + ra * N + t];
    }
    const float4* xg = reinterpret_cast<const float4*>(x + (size_t)f * N * 64);
    float4* xs4 = reinterpret_cast<float4*>(x_s);
    for (int idx = tid; idx < N * 16; idx += 256) xs4[idx] = xg[idx];
    __syncthreads();

    const int tx = tid & 7;      // 8 cols (4 f32x2 pairs)
    const int ty = tid >> 3;     // rows ty + 32*i

    u64 acc[RT][4];
#pragma unroll
    for (int i = 0; i < RT; i++)
#pragma unroll
        for (int q = 0; q < 4; q++) acc[i][q] = 0ull;

#pragma unroll 2
    for (int t = 0; t < N; t++) {
        const ulonglong2* xb = reinterpret_cast<const ulonglong2*>(x_s + t * 64 + 8 * tx);
        ulonglong2 b01 = xb[0];
        ulonglong2 b23 = xb[1];
#pragma unroll
        for (int i = 0; i < RT; i++) {
            u64 a = pk2(D_s[(ty + 32 * i) * (N + 1) + t]);
            fma2(acc[i][0], a, b01.x); fma2(acc[i][1], a, b01.y);
            fma2(acc[i][2], a, b23.x); fma2(acc[i][3], a, b23.y);
        }
    }

#pragma unroll
    for (int i = 0; i < RT; i++) {
        int rp = ty + 32 * i;
        int ra = rp + (rp > 0);
        int k = ra >> 1, ri = ra & 1;
        ulonglong2* dst = reinterpret_cast<ulonglong2*>(
            g_X + XOFF + ((size_t)(k * F + f) * 2 + ri) * 64 + 8 * tx);
        dst[0] = make_ulonglong2(acc[i][0], acc[i][1]);
        dst[1] = make_ulonglong2(acc[i][2], acc[i][3]);
    }

    // zero rows: (k=0, ri=1) and (k=N/2, ri=1)
    if (tid < 32) {
        int kz = (tid >> 4) ? (N / 2) : 0;
        int q = tid & 15;
        *reinterpret_cast<float4*>(
            g_X + XOFF + ((size_t)(kz * F + f) * 2 + 1) * 64 + 4 * q) =
            make_float4(0.f, 0.f, 0.f, 0.f);
    }
}

// ---------------- stage 2: per-bin [64f x 128] x [128 x 64] + leaky ----------------
__global__ void k_stage2(int xoff, int goff, int zoff, int F, int bins) {
    extern __shared__ float sm[];
    float* A_s = sm;               // 64 rows, stride 132
    float* B_s = sm + 64 * 132;    // 128 x 64
    const int tid = threadIdx.x;
    const int k = blockIdx.y;
    const int f0 = blockIdx.x * 64;

    const float4* Xg = reinterpret_cast<const float4*>(g_X + xoff + ((size_t)k * F + f0) * 128);
    float4* A4 = reinterpret_cast<float4*>(A_s);
    for (int idx = tid; idx < 64 * 32; idx += 256)
        A4[(idx >> 5) * 33 + (idx & 31)] = Xg[idx];
    const float4* Gg = reinterpret_cast<const float4*>(g_G + goff + (size_t)k * 8192);
    float4* B4 = reinterpret_cast<float4*>(B_s);
    for (int idx = tid; idx < 2048; idx += 256) B4[idx] = Gg[idx];
    __syncthreads();

    const int tx = tid & 7;
    const int ty = tid >> 3;    // rows ty, ty+32

    u64 acc[2][4];
#pragma unroll
    for (int i = 0; i < 2; i++)
#pragma unroll
        for (int q = 0; q < 4; q++) acc[i][q] = 0ull;

#pragma unroll 2
    for (int j = 0; j < 128; j++) {
        const ulonglong2* Bp = reinterpret_cast<const ulonglong2*>(B_s + j * 64 + 8 * tx);
        ulonglong2 b01 = Bp[0];
        ulonglong2 b23 = Bp[1];
        u64 a0 = pk2(A_s[ty * 132 + j]);
        u64 a1 = pk2(A_s[(ty + 32) * 132 + j]);
        fma2(acc[0][0], a0, b01.x); fma2(acc[0][1], a0, b01.y);
        fma2(acc[0][2], a0, b23.x); fma2(acc[0][3], a0, b23.y);
        fma2(acc[1][0], a1, b01.x); fma2(acc[1][1], a1, b01.y);
        fma2(acc[1][2], a1, b23.x); fma2(acc[1][3], a1, b23.y);
    }

#pragma unroll
    for (int i = 0; i < 2; i++) {
        int f = f0 + ty + 32 * i;
        float* zp = g_Z + zoff + ((size_t)f * bins + k) * 64;
        float2 u0 = up(acc[i][0]), u1 = up(acc[i][1]);
        float2 u2 = up(acc[i][2]), u3 = up(acc[i][3]);
        // even lanes -> ri=0 (col 4tx+q), odd lanes -> ri=1
        *reinterpret_cast<float4*>(zp + 4 * tx) =
            make_float4(lk(u0.x), lk(u1.x), lk(u2.x), lk(u3.x));
        *reinterpret_cast<float4*>(zp + 32 + 4 * tx) =
            make_float4(lk(u0.y), lk(u1.y), lk(u2.y), lk(u3.y));
    }
}

// ---------------- stage 3: irfft + bias ----------------
// C cols 1 and N+1 are zero -> compact j-loop to N iterations.
template <int N, int GG, int COFF, int ZOFF, int OOFF>
__global__ void k_stage3(float* __restrict__ out, const float* __restrict__ bias) {
    constexpr int BINS = N / 2 + 1;
    constexpr int R = 2 * BINS;
    constexpr int FPC = 128 / N;
    constexpr int TPF = 256 / FPC;
    extern __shared__ float sm[];
    float* C_s = sm;                   // N x (N+1) compact
    float* Z_s = sm + N * (N + 1);     // FPC x (R*32)
    const int tid = threadIdx.x;

    for (int idx = tid; idx < N * N; idx += 256) {
        int t = idx / N, jj = idx % N;
        int ja = jj + (jj > 0);
        C_s[t * (N + 1) + jj] = g_C[COFF + t * R + ja];
    }
    const int fl = tid / TPF;
    const int tx = tid & 3;                    // 8 cols of the 32
    const int tyy = (tid >> 2) & (N / 2 - 1);  // row pair

    const float4 b0v = *reinterpret_cast<const float4*>(bias + OOFF + 8 * tx);
    const float4 b1v = *reinterpret_cast<const float4*>(bias + OOFF + 8 * tx + 4);
    const u64 bv0 = pk(b0v.x, b0v.y), bv1 = pk(b0v.z, b0v.w);
    const u64 bv2 = pk(b1v.x, b1v.y), bv3 = pk(b1v.z, b1v.w);

    for (int g = 0; g < GG; g++) {
        const int f0 = (blockIdx.x * GG + g) * FPC;
        __syncthreads();
        const float4* Zg = reinterpret_cast<const float4*>(g_Z + ZOFF + (size_t)f0 * BINS * 64);
        float4* Z4 = reinterpret_cast<float4*>(Z_s);
        for (int idx = tid; idx < FPC * BINS * 16; idx += 256) Z4[idx] = Zg[idx];
        __syncthreads();

        const float* Zf = Z_s + fl * (R * 32);
        u64 acc[2][4];
#pragma unroll
        for (int rr = 0; rr < 2; rr++) {
            acc[rr][0] = bv0; acc[rr][1] = bv1; acc[rr][2] = bv2; acc[rr][3] = bv3;
        }

#pragma unroll 2
        for (int j = 0; j < N; j++) {
            int ja = j + (j > 0);
            const ulonglong2* Zp = reinterpret_cast<const ulonglong2*>(Zf + ja * 32 + 8 * tx);
            ulonglong2 z01 = Zp[0];
            ulonglong2 z23 = Zp[1];
            u64 a0 = pk2(C_s[(2 * tyy) * (N + 1) + j]);
            u64 a1 = pk2(C_s[(2 * tyy + 1) * (N + 1) + j]);
            fma2(acc[0][0], a0, z01.x); fma2(acc[0][1], a0, z01.y);
            fma2(acc[0][2], a0, z23.x); fma2(acc[0][3], a0, z23.y);
            fma2(acc[1][0], a1, z01.x); fma2(acc[1][1], a1, z01.y);
            fma2(acc[1][2], a1, z23.x); fma2(acc[1][3], a1, z23.y);
        }

        const int f = f0 + fl;
#pragma unroll
        for (int rr = 0; rr < 2; rr++) {
            int t = 2 * tyy + rr;
            ulonglong2* op = reinterpret_cast<ulonglong2*>(
                out + ((size_t)f * N + t) * 96 + OOFF + 8 * tx);
            op[0] = make_ulonglong2(acc[rr][0], acc[rr][1]);
            op[1] = make_ulonglong2(acc[rr][2], acc[rr][3]);
        }
    }
}

// ---------------- launch ----------------
extern "C" void kernel_launch(void* const* d_in, const int* in_sizes, int n_in,
                              void* d_out, int out_size) {
    const float* x    = (const float*)d_in[0];
    const float* kr   = (const float*)d_in[1];
    const float* ki   = (const float*)d_in[2];
    const float* bias = (const float*)d_in[3];
    float* out = (float*)d_out;

    const int s1_32  = (32 * 33 + 32 * 64) * 4;     // 12416
    const int s1_64  = (64 * 65 + 64 * 64) * 4;     // 33024
    const int s1_128 = (128 * 129 + 128 * 64) * 4;  // 98816
    const int s2     = (64 * 132 + 128 * 64) * 4;   // 66560
    const int s3_32  = (32 * 33 + 4 * 68 * 32) * 4; // 39040
    const int s3_64  = (64 * 65 + 2 * 66 * 32) * 4; // 33536
    const int s3_128 = (128 * 129 + 130 * 32) * 4;  // 82688

    cudaFuncSetAttribute(k_stage1<128, 5312, 8781824, 512>,
                         cudaFuncAttributeMaxDynamicSharedMemorySize, s1_128);
    cudaFuncSetAttribute(k_stage2, cudaFuncAttributeMaxDynamicSharedMemorySize, s2);
    cudaFuncSetAttribute(k_stage3<128, 2, 5312, 4390912, 64>,
                         cudaFuncAttributeMaxDynamicSharedMemorySize, s3_128);

    k_build_dft<<<dim3(65, 3), 256>>>();
    k_build_G<<<dim3(520, 3), 256>>>(kr, ki);

    k_stage1<32, 0, 0, 2048><<<2048, 256, s1_32>>>(x);
    k_stage1<64, 1088, 4456448, 1024><<<1024, 256, s1_64>>>(x);
    k_stage1<128, 5312, 8781824, 512><<<512, 256, s1_128>>>(x);

    k_stage2<<<dim3(32, 17), 256, s2>>>(0, 0, 0, 2048, 17);
    k_stage2<<<dim3(16, 33), 256, s2>>>(4456448, 139264, 2228224, 1024, 33);
    k_stage2<<<dim3(8, 65), 256, s2>>>(8781824, 409600, 4390912, 512, 65);

    k_stage3<32, 2, 0, 0, 0><<<256, 256, s3_32>>>(out, bias);
    k_stage3<64, 2, 1088, 2228224, 32><<<256, 256, s3_64>>>(out, bias);
    k_stage3<128, 2, 5312, 4390912, 64><<<256, 256, s3_128>>>(out, bias);
}

// round 7
// speedup vs baseline: 1.6725x; 1.6725x over previous
#include <cuda_runtime.h>
#include <math.h>

#define CIN 64
#define COUT_PER 32
#define LALPHA 0.2f

__device__ __forceinline__ float lk(float v) { return v > 0.f ? v : LALPHA * v; }

#define FMA4(ACC, S, B) { ACC.x += (S)*(B).x; ACC.y += (S)*(B).y; ACC.z += (S)*(B).z; ACC.w += (S)*(B).w; }

// ---------------- static device scratch ----------------
// D (forward DFT [r][t]) / C (inverse DFT [t][j]); offs: fft32->0, fft64->1088, fft128->5312
__device__ float g_D[21952];
__device__ float g_C[21952];
// G[k][j=ri*64+c][o2=2o+rio]; offs 0 / 139264 / 409600
__device__ float g_G[942080];
// X[k][f][ri][c]; offs 0 / 4456448 / 8781824
__device__ float g_X[13041664];
// Z[f][j=2k+ri][o]; offs 0 / 2228224 / 4390912
__device__ float g_Z[6520832];

// ---------------- precompute ----------------
__global__ void k_build_dft() {
    int ffti = blockIdx.y;
    int N = 32 << ffti;
    int bins = N / 2 + 1;
    int R = 2 * bins;
    int total = R * N;
    int off = (ffti == 0) ? 0 : (ffti == 1 ? 1088 : 5312);
    int stride = gridDim.x * blockDim.x;
    for (int idx = blockIdx.x * blockDim.x + threadIdx.x; idx < total; idx += stride) {
        {   // D [r][t]
            int r = idx / N, t = idx % N;
            int k = r >> 1, ri = r & 1;
            int m = (k * t) % N;
            float s, c;
            sincospif(2.0f * (float)m / (float)N, &s, &c);
            g_D[off + idx] = ri ? -s : c;
        }
        {   // C [t][j]
            int t = idx / R, j = idx % R;
            int k = j >> 1, ri = j & 1;
            int m = (k * t) % N;
            float s, c;
            sincospif(2.0f * (float)m / (float)N, &s, &c);
            float w = (k == 0 || k == bins - 1) ? 1.0f : 2.0f;
            g_C[off + idx] = (ri ? -s : c) * (w / (float)N);
        }
    }
}

__global__ void k_build_G(const float* __restrict__ kr, const float* __restrict__ ki) {
    int ffti = blockIdx.y;
    int N = 32 << ffti;
    int bins = N / 2 + 1;
    int goff = (ffti == 0) ? 0 : (ffti == 1 ? 139264 : 409600);
    int total = bins * CIN * COUT_PER;
    int stride = gridDim.x * blockDim.x;
    for (int idx = blockIdx.x * blockDim.x + threadIdx.x; idx < total; idx += stride) {
        int k = idx / (CIN * COUT_PER);
        int rem = idx % (CIN * COUT_PER);
        int c = rem / COUT_PER, o = rem % COUT_PER;
        float vr, vi;
        if (bins == 33) {
            vr = kr[k * 2048 + rem];
            vi = ki[k * 2048 + rem];
        } else {
            float src = (k + 0.5f) * (33.0f / (float)bins) - 0.5f;
            float fl = floorf(src);
            int i0 = (int)fl;
            float f = src - fl;
            int i0c = i0 < 0 ? 0 : i0;
            int i1c = i0 + 1 > 32 ? 32 : i0 + 1;
            vr = (1.0f - f) * kr[i0c * 2048 + rem] + f * kr[i1c * 2048 + rem];
            vi = (1.0f - f) * ki[i0c * 2048 + rem] + f * ki[i1c * 2048 + rem];
        }
        float* Gk = g_G + goff + k * 8192;
        Gk[c * 64 + 2 * o]            = vr;
        Gk[c * 64 + 2 * o + 1]        = vi;
        Gk[(64 + c) * 64 + 2 * o]     = -vi;
        Gk[(64 + c) * 64 + 2 * o + 1] = vr;
    }
}

// ---------------- stage 1: forward DFT ----------------
// D rows 1 and N+1 are identically zero -> compute exactly N rows (remap 0,2..N).
// CTA computes ROWS = RPT*16 rows of one frame (gridDim.y splits rows for N=128).
template <int N, int RPT, int DOFF, int XOFF, int F>
__launch_bounds__(256)
__global__ void k_stage1(const float* __restrict__ x) {
    constexpr int SD = N + 4;
    constexpr int ROWS = RPT * 16;
    extern __shared__ float sm[];
    float* D_s = sm;                 // ROWS x SD (t contiguous)
    float* x_s = sm + ROWS * SD;     // N x 64
    const int tid = threadIdx.x;
    const int f = blockIdx.x;
    const int r0 = blockIdx.y * ROWS;

    for (int idx = tid; idx < ROWS * N; idx += 256) {
        int rl = idx / N, t = idx % N;
        int rp = r0 + rl;
        int ra = rp + (rp > 0);
        D_s[rl * SD + t] = g_D[DOFF + ra * N + t];
    }
    const float4* xg = reinterpret_cast<const float4*>(x + (size_t)f * N * 64);
    float4* xs4 = reinterpret_cast<float4*>(x_s);
    for (int idx = tid; idx < N * 16; idx += 256) xs4[idx] = xg[idx];
    __syncthreads();

    const int tx = tid & 15;     // 4 cols
    const int ty = tid >> 4;     // rows ty*RPT + i

    float4 acc[RPT];
#pragma unroll
    for (int i = 0; i < RPT; i++) acc[i] = make_float4(0.f, 0.f, 0.f, 0.f);

#pragma unroll 2
    for (int tc = 0; tc < N; tc += 4) {
        float4 a[RPT];
#pragma unroll
        for (int i = 0; i < RPT; i++)
            a[i] = *reinterpret_cast<const float4*>(&D_s[(ty * RPT + i) * SD + tc]);
        float4 b0 = xs4[(tc + 0) * 16 + tx];
        float4 b1 = xs4[(tc + 1) * 16 + tx];
        float4 b2 = xs4[(tc + 2) * 16 + tx];
        float4 b3 = xs4[(tc + 3) * 16 + tx];
#pragma unroll
        for (int i = 0; i < RPT; i++) {
            FMA4(acc[i], a[i].x, b0); FMA4(acc[i], a[i].y, b1);
            FMA4(acc[i], a[i].z, b2); FMA4(acc[i], a[i].w, b3);
        }
    }

#pragma unroll
    for (int i = 0; i < RPT; i++) {
        int rp = r0 + ty * RPT + i;
        int ra = rp + (rp > 0);
        int k = ra >> 1, ri = ra & 1;
        *reinterpret_cast<float4*>(
            g_X + XOFF + ((size_t)(k * F + f) * 2 + ri) * 64 + 4 * tx) = acc[i];
    }

    // zero rows: (k=0, ri=1) and (k=N/2, ri=1)
    if (blockIdx.y == 0 && tid < 32) {
        int kz = (tid >> 4) ? (N / 2) : 0;
        int q = tid & 15;
        *reinterpret_cast<float4*>(
            g_X + XOFF + ((size_t)(kz * F + f) * 2 + 1) * 64 + 4 * q) =
            make_float4(0.f, 0.f, 0.f, 0.f);
    }
}

// ---------------- stage 2: per-bin [64f x 128] x [128 x 64] + leaky ----------------
__launch_bounds__(256)
__global__ void k_stage2(int xoff, int goff, int zoff, int F, int bins) {
    extern __shared__ float sm[];
    float* A_s = sm;               // 64 rows x 132 (j contiguous)
    float* B_s = sm + 64 * 132;    // 128 x 64
    const int tid = threadIdx.x;
    const int k = blockIdx.y;
    const int f0 = blockIdx.x * 64;

    const float4* Xg = reinterpret_cast<const float4*>(g_X + xoff + ((size_t)k * F + f0) * 128);
    float4* A4 = reinterpret_cast<float4*>(A_s);
    for (int idx = tid; idx < 64 * 32; idx += 256)
        A4[(idx >> 5) * 33 + (idx & 31)] = Xg[idx];
    const float4* Gg = reinterpret_cast<const float4*>(g_G + goff + (size_t)k * 8192);
    float4* B4 = reinterpret_cast<float4*>(B_s);
    for (int idx = tid; idx < 2048; idx += 256) B4[idx] = Gg[idx];
    __syncthreads();

    const int tx = tid & 15;   // 4 cols (o2 = 4tx..4tx+3)
    const int ty = tid >> 4;   // rows ty*4 + i

    float4 acc[4];
#pragma unroll
    for (int i = 0; i < 4; i++) acc[i] = make_float4(0.f, 0.f, 0.f, 0.f);

#pragma unroll 2
    for (int jc = 0; jc < 128; jc += 4) {
        float4 a[4];
#pragma unroll
        for (int i = 0; i < 4; i++)
            a[i] = *reinterpret_cast<const float4*>(&A_s[(ty * 4 + i) * 132 + jc]);
        float4 b0 = *reinterpret_cast<const float4*>(&B_s[(jc + 0) * 64 + 4 * tx]);
        float4 b1 = *reinterpret_cast<const float4*>(&B_s[(jc + 1) * 64 + 4 * tx]);
        float4 b2 = *reinterpret_cast<const float4*>(&B_s[(jc + 2) * 64 + 4 * tx]);
        float4 b3 = *reinterpret_cast<const float4*>(&B_s[(jc + 3) * 64 + 4 * tx]);
#pragma unroll
        for (int i = 0; i < 4; i++) {
            FMA4(acc[i], a[i].x, b0); FMA4(acc[i], a[i].y, b1);
            FMA4(acc[i], a[i].z, b2); FMA4(acc[i], a[i].w, b3);
        }
    }

#pragma unroll
    for (int i = 0; i < 4; i++) {
        int f = f0 + ty * 4 + i;
        float* zp = g_Z + zoff + ((size_t)f * bins + k) * 64;
        // o2 = 4tx+q: q even -> ri=0 (o=2tx+q/2), q odd -> ri=1
        *reinterpret_cast<float2*>(zp + 2 * tx)      = make_float2(lk(acc[i].x), lk(acc[i].z));
        *reinterpret_cast<float2*>(zp + 32 + 2 * tx) = make_float2(lk(acc[i].y), lk(acc[i].w));
    }
}

// ---------------- stage 3: irfft + bias ----------------
// C cols 1 and N+1 are zero -> compact j-loop to N iterations (stored compact).
template <int N, int FPC, int COFF, int ZOFF, int OOFF>
__launch_bounds__(256)
__global__ void k_stage3(float* __restrict__ out, const float* __restrict__ bias) {
    constexpr int BINS = N / 2 + 1;
    constexpr int R = 2 * BINS;
    constexpr int SD = N + 4;
    constexpr int TPF = 256 / FPC;   // = 2N
    extern __shared__ float sm[];
    float* C_s = sm;                 // N x SD compact (j contiguous)
    float* Z_s = sm + N * SD;        // FPC x (R*32)
    const int tid = threadIdx.x;

    for (int idx = tid; idx < N * N; idx += 256) {
        int t = idx / N, jj = idx % N;
        int ja = jj + (jj > 0);
        C_s[t * SD + jj] = g_C[COFF + t * R + ja];
    }
    const int f0 = blockIdx.x * FPC;
    const float4* Zg = reinterpret_cast<const float4*>(g_Z + ZOFF + (size_t)f0 * BINS * 64);
    float4* Z4 = reinterpret_cast<float4*>(Z_s);
    for (int idx = tid; idx < FPC * BINS * 16; idx += 256) Z4[idx] = Zg[idx];
    __syncthreads();

    const int fl = tid / TPF;
    const int tf = tid % TPF;
    const int txc = tf & 7;          // 4 cols (of 32)
    const int tyr = tf >> 3;         // rows tyr*4 + i

    const float4 bv = *reinterpret_cast<const float4*>(bias + OOFF + 4 * txc);
    float4 acc[4];
#pragma unroll
    for (int i = 0; i < 4; i++) acc[i] = bv;

    const float* Zf = Z_s + fl * (R * 32);

#pragma unroll 2
    for (int jc = 0; jc < N; jc += 4) {
        float4 a[4];
#pragma unroll
        for (int i = 0; i < 4; i++)
            a[i] = *reinterpret_cast<const float4*>(&C_s[(tyr * 4 + i) * SD + jc]);
        float4 b[4];
#pragma unroll
        for (int jj = 0; jj < 4; jj++) {
            int ja = jc + jj + ((jc + jj) > 0);
            b[jj] = *reinterpret_cast<const float4*>(&Zf[ja * 32 + 4 * txc]);
        }
#pragma unroll
        for (int i = 0; i < 4; i++) {
            FMA4(acc[i], a[i].x, b[0]); FMA4(acc[i], a[i].y, b[1]);
            FMA4(acc[i], a[i].z, b[2]); FMA4(acc[i], a[i].w, b[3]);
        }
    }

    const int f = f0 + fl;
#pragma unroll
    for (int i = 0; i < 4; i++) {
        int t = tyr * 4 + i;
        *reinterpret_cast<float4*>(out + ((size_t)f * N + t) * 96 + OOFF + 4 * txc) = acc[i];
    }
}

// ---------------- launch ----------------
extern "C" void kernel_launch(void* const* d_in, const int* in_sizes, int n_in,
                              void* d_out, int out_size) {
    const float* x    = (const float*)d_in[0];
    const float* kr   = (const float*)d_in[1];
    const float* ki   = (const float*)d_in[2];
    const float* bias = (const float*)d_in[3];
    float* out = (float*)d_out;

    const int s1_32  = (32 * 36 + 32 * 64) * 4;     // 12800
    const int s1_64  = (64 * 68 + 64 * 64) * 4;     // 33792
    const int s1_128 = (64 * 132 + 128 * 64) * 4;   // 66560
    const int s2     = (64 * 132 + 128 * 64) * 4;   // 66560
    const int s3_32  = (32 * 36 + 4 * 34 * 32) * 4; // 22016
    const int s3_64  = (64 * 68 + 2 * 66 * 32) * 4; // 34304
    const int s3_128 = (128 * 132 + 130 * 32) * 4;  // 84224

    cudaFuncSetAttribute(k_stage1<128, 4, 5312, 8781824, 512>,
                         cudaFuncAttributeMaxDynamicSharedMemorySize, s1_128);
    cudaFuncSetAttribute(k_stage2, cudaFuncAttributeMaxDynamicSharedMemorySize, s2);
    cudaFuncSetAttribute(k_stage3<128, 1, 5312, 4390912, 64>,
                         cudaFuncAttributeMaxDynamicSharedMemorySize, s3_128);

    k_build_dft<<<dim3(65, 3), 256>>>();
    k_build_G<<<dim3(520, 3), 256>>>(kr, ki);

    k_stage1<32, 2, 0, 0, 2048><<<2048, 256, s1_32>>>(x);
    k_stage1<64, 4, 1088, 4456448, 1024><<<1024, 256, s1_64>>>(x);
    k_stage1<128, 4, 5312, 8781824, 512><<<dim3(512, 2), 256, s1_128>>>(x);

    k_stage2<<<dim3(32, 17), 256, s2>>>(0, 0, 0, 2048, 17);
    k_stage2<<<dim3(16, 33), 256, s2>>>(4456448, 139264, 2228224, 1024, 33);
    k_stage2<<<dim3(8, 65), 256, s2>>>(8781824, 409600, 4390912, 512, 65);

    k_stage3<32, 4, 0, 0, 0><<<512, 256, s3_32>>>(out, bias);
    k_stage3<64, 2, 1088, 2228224, 32><<<512, 256, s3_64>>>(out, bias);
    k_stage3<128, 1, 5312, 4390912, 64><<<512, 256, s3_128>>>(out, bias);
}

// round 10
// speedup vs baseline: 1.9790x; 1.1833x over previous
#include <cuda_runtime.h>
#include <cuda_bf16.h>
#include <math.h>
#include <cstdint>

#define CIN 64
#define COUT_PER 32
#define LALPHA 0.2f

__device__ __forceinline__ float lk(float v) { return v > 0.f ? v : LALPHA * v; }

#define FMA4(ACC, S, B) { ACC.x += (S)*(B).x; ACC.y += (S)*(B).y; ACC.z += (S)*(B).z; ACC.w += (S)*(B).w; }

__device__ __forceinline__ uint32_t smem_u32(const void* p) {
    uint32_t a;
    asm("{ .reg .u64 t; cvta.to.shared.u64 t, %1; cvt.u32.u64 %0, t; }" : "=r"(a) : "l"(p));
    return a;
}
__device__ __forceinline__ uint32_t pkbf(float x, float y) {
    __nv_bfloat162 h = __floats2bfloat162_rn(x, y);
    return *reinterpret_cast<uint32_t*>(&h);
}
#define LDSM_X4(R, ADDR) \
    asm volatile("ldmatrix.sync.aligned.m8n8.x4.shared.b16 {%0,%1,%2,%3}, [%4];" \
        : "=r"((R)[0]), "=r"((R)[1]), "=r"((R)[2]), "=r"((R)[3]) : "r"(ADDR))
#define LDSM_X2(R, ADDR) \
    asm volatile("ldmatrix.sync.aligned.m8n8.x2.shared.b16 {%0,%1}, [%2];" \
        : "=r"((R)[0]), "=r"((R)[1]) : "r"(ADDR))
#define MMA_BF16(ACC, A, B) \
    asm volatile("mma.sync.aligned.m16n8k16.row.col.f32.bf16.bf16.f32 " \
        "{%0,%1,%2,%3}, {%4,%5,%6,%7}, {%8,%9}, {%0,%1,%2,%3};" \
        : "+f"((ACC)[0]), "+f"((ACC)[1]), "+f"((ACC)[2]), "+f"((ACC)[3]) \
        : "r"((A)[0]), "r"((A)[1]), "r"((A)[2]), "r"((A)[3]), "r"((B)[0]), "r"((B)[1]))

// ---------------- static device scratch ----------------
__device__ float g_D[21952];
__device__ float g_C[21952];
// GT[k][o2(64)][j(128)] fp32 (K-major = B col-major for mma); offs 0 / 139264 / 409600
__device__ float g_G[942080];
// X[k][f][ri][c]; offs 0 / 4456448 / 8781824
__device__ float g_X[13041664];
// Z[f][j=2k+ri][o]; offs 0 / 2228224 / 4390912
__device__ float g_Z[6520832];

// ---------------- precompute ----------------
__global__ void k_build_dft() {
    int ffti = blockIdx.y;
    int N = 32 << ffti;
    int bins = N / 2 + 1;
    int R = 2 * bins;
    int total = R * N;
    int off = (ffti == 0) ? 0 : (ffti == 1 ? 1088 : 5312);
    int stride = gridDim.x * blockDim.x;
    for (int idx = blockIdx.x * blockDim.x + threadIdx.x; idx < total; idx += stride) {
        {   // D [r][t]
            int r = idx / N, t = idx % N;
            int k = r >> 1, ri = r & 1;
            int m = (k * t) % N;
            float s, c;
            sincospif(2.0f * (float)m / (float)N, &s, &c);
            g_D[off + idx] = ri ? -s : c;
        }
        {   // C [t][j]
            int t = idx / R, j = idx % R;
            int k = j >> 1, ri = j & 1;
            int m = (k * t) % N;
            float s, c;
            sincospif(2.0f * (float)m / (float)N, &s, &c);
            float w = (k == 0 || k == bins - 1) ? 1.0f : 2.0f;
            g_C[off + idx] = (ri ? -s : c) * (w / (float)N);
        }
    }
}

// GT[o2][j]: GT[2o][c]=vr, GT[2o+1][c]=vi, GT[2o][64+c]=-vi, GT[2o+1][64+c]=vr
__global__ void k_build_G(const float* __restrict__ kr, const float* __restrict__ ki) {
    int ffti = blockIdx.y;
    int N = 32 << ffti;
    int bins = N / 2 + 1;
    int goff = (ffti == 0) ? 0 : (ffti == 1 ? 139264 : 409600);
    int total = bins * CIN * COUT_PER;
    int stride = gridDim.x * blockDim.x;
    for (int idx = blockIdx.x * blockDim.x + threadIdx.x; idx < total; idx += stride) {
        int k = idx / (CIN * COUT_PER);
        int rem = idx % (CIN * COUT_PER);
        int c = rem / COUT_PER, o = rem % COUT_PER;
        float vr, vi;
        if (bins == 33) {
            vr = kr[k * 2048 + rem];
            vi = ki[k * 2048 + rem];
        } else {
            float src = (k + 0.5f) * (33.0f / (float)bins) - 0.5f;
            float fl = floorf(src);
            int i0 = (int)fl;
            float f = src - fl;
            int i0c = i0 < 0 ? 0 : i0;
            int i1c = i0 + 1 > 32 ? 32 : i0 + 1;
            vr = (1.0f - f) * kr[i0c * 2048 + rem] + f * kr[i1c * 2048 + rem];
            vi = (1.0f - f) * ki[i0c * 2048 + rem] + f * ki[i1c * 2048 + rem];
        }
        float* Gk = g_G + goff + k * 8192;
        Gk[(2 * o) * 128 + c]          = vr;
        Gk[(2 * o + 1) * 128 + c]      = vi;
        Gk[(2 * o) * 128 + 64 + c]     = -vi;
        Gk[(2 * o + 1) * 128 + 64 + c] = vr;
    }
}

// ---------------- stage 1: forward DFT (scalar, unchanged) ----------------
template <int N, int RPT, int DOFF, int XOFF, int F>
__launch_bounds__(256)
__global__ void k_stage1(const float* __restrict__ x) {
    constexpr int SD = N + 4;
    constexpr int ROWS = RPT * 16;
    extern __shared__ float sm[];
    float* D_s = sm;
    float* x_s = sm + ROWS * SD;
    const int tid = threadIdx.x;
    const int f = blockIdx.x;
    const int r0 = blockIdx.y * ROWS;

    for (int idx = tid; idx < ROWS * N; idx += 256) {
        int rl = idx / N, t = idx % N;
        int rp = r0 + rl;
        int ra = rp + (rp > 0);
        D_s[rl * SD + t] = g_D[DOFF + ra * N + t];
    }
    const float4* xg = reinterpret_cast<const float4*>(x + (size_t)f * N * 64);
    float4* xs4 = reinterpret_cast<float4*>(x_s);
    for (int idx = tid; idx < N * 16; idx += 256) xs4[idx] = xg[idx];
    __syncthreads();

    const int tx = tid & 15;
    const int ty = tid >> 4;

    float4 acc[RPT];
#pragma unroll
    for (int i = 0; i < RPT; i++) acc[i] = make_float4(0.f, 0.f, 0.f, 0.f);

#pragma unroll 2
    for (int tc = 0; tc < N; tc += 4) {
        float4 a[RPT];
#pragma unroll
        for (int i = 0; i < RPT; i++)
            a[i] = *reinterpret_cast<const float4*>(&D_s[(ty * RPT + i) * SD + tc]);
        float4 b0 = xs4[(tc + 0) * 16 + tx];
        float4 b1 = xs4[(tc + 1) * 16 + tx];
        float4 b2 = xs4[(tc + 2) * 16 + tx];
        float4 b3 = xs4[(tc + 3) * 16 + tx];
#pragma unroll
        for (int i = 0; i < RPT; i++) {
            FMA4(acc[i], a[i].x, b0); FMA4(acc[i], a[i].y, b1);
            FMA4(acc[i], a[i].z, b2); FMA4(acc[i], a[i].w, b3);
        }
    }

#pragma unroll
    for (int i = 0; i < RPT; i++) {
        int rp = r0 + ty * RPT + i;
        int ra = rp + (rp > 0);
        int k = ra >> 1, ri = ra & 1;
        *reinterpret_cast<float4*>(
            g_X + XOFF + ((size_t)(k * F + f) * 2 + ri) * 64 + 4 * tx) = acc[i];
    }

    if (blockIdx.y == 0 && tid < 32) {
        int kz = (tid >> 4) ? (N / 2) : 0;
        int q = tid & 15;
        *reinterpret_cast<float4*>(
            g_X + XOFF + ((size_t)(kz * F + f) * 2 + 1) * 64 + 4 * q) =
            make_float4(0.f, 0.f, 0.f, 0.f);
    }
}

// ---------------- stage 2: mma.sync bf16-split, one bin x 128 frames per CTA ------
// D[128f x 64o2] = A[128f x 128j] @ B[64o2 x 128j]^T via Ah*Bh + Ah*Bl + Al*Bh
__launch_bounds__(256)
__global__ void k_stage2_tc(int xoff, int goff, int zoff, int F, int bins) {
    constexpr int SDB = 136;                 // bf16 row stride (272B: 16B-aligned, conflict-free)
    extern __shared__ char smem[];
    __nv_bfloat16* Ah = reinterpret_cast<__nv_bfloat16*>(smem);
    __nv_bfloat16* Al = Ah + 128 * SDB;
    __nv_bfloat16* Bh = Al + 128 * SDB;
    __nv_bfloat16* Bl = Bh + 64 * SDB;

    const int tid = threadIdx.x;
    const int warp = tid >> 5, lane = tid & 31;
    const int k = blockIdx.y;
    const int f0 = blockIdx.x * 128;

    // ---- convert A (X rows) to bf16 hi/lo in smem ----
    const float4* Xg = reinterpret_cast<const float4*>(g_X + xoff + ((size_t)k * F + f0) * 128);
    for (int idx = tid; idx < 128 * 32; idx += 256) {
        int row = idx >> 5, q = idx & 31;
        float4 v = Xg[idx];
        float hx = __bfloat162float(__float2bfloat16(v.x));
        float hy = __bfloat162float(__float2bfloat16(v.y));
        float hz = __bfloat162float(__float2bfloat16(v.z));
        float hw = __bfloat162float(__float2bfloat16(v.w));
        uint2 hi = make_uint2(pkbf(v.x, v.y), pkbf(v.z, v.w));
        uint2 lo = make_uint2(pkbf(v.x - hx, v.y - hy), pkbf(v.z - hz, v.w - hw));
        *reinterpret_cast<uint2*>(&Ah[row * SDB + 4 * q]) = hi;
        *reinterpret_cast<uint2*>(&Al[row * SDB + 4 * q]) = lo;
    }
    // ---- convert B (GT rows, [o2][j] = col-major for mma) ----
    const float4* Gg = reinterpret_cast<const float4*>(g_G + goff + (size_t)k * 8192);
    for (int idx = tid; idx < 64 * 32; idx += 256) {
        int row = idx >> 5, q = idx & 31;
        float4 v = Gg[idx];
        float hx = __bfloat162float(__float2bfloat16(v.x));
        float hy = __bfloat162float(__float2bfloat16(v.y));
        float hz = __bfloat162float(__float2bfloat16(v.z));
        float hw = __bfloat162float(__float2bfloat16(v.w));
        uint2 hi = make_uint2(pkbf(v.x, v.y), pkbf(v.z, v.w));
        uint2 lo = make_uint2(pkbf(v.x - hx, v.y - hy), pkbf(v.z - hz, v.w - hw));
        *reinterpret_cast<uint2*>(&Bh[row * SDB + 4 * q]) = hi;
        *reinterpret_cast<uint2*>(&Bl[row * SDB + 4 * q]) = lo;
    }
    __syncthreads();

    // ---- mma mainloop: warp owns rows m0..m0+15, all 64 cols ----
    const int m0 = warp * 16;
    float acc[8][4];
#pragma unroll
    for (int nt = 0; nt < 8; nt++)
#pragma unroll
        for (int q = 0; q < 4; q++) acc[nt][q] = 0.f;

    const uint32_t aoff = (uint32_t)((m0 + (lane & 15)) * SDB + ((lane >> 4) << 3));
    const uint32_t a_addr_h = smem_u32(Ah) + 2 * aoff;
    const uint32_t a_addr_l = smem_u32(Al) + 2 * aoff;
    const uint32_t boff = (uint32_t)((lane & 7) * SDB + (((lane >> 3) & 1) << 3));
    const uint32_t b_addr_h = smem_u32(Bh) + 2 * boff;
    const uint32_t b_addr_l = smem_u32(Bl) + 2 * boff;

#pragma unroll
    for (int kc = 0; kc < 8; kc++) {
        uint32_t ah[4], al[4];
        LDSM_X4(ah, a_addr_h + 32 * kc);
        LDSM_X4(al, a_addr_l + 32 * kc);
#pragma unroll
        for (int nt = 0; nt < 8; nt++) {
            uint32_t bh[2], bl[2];
            LDSM_X2(bh, b_addr_h + (uint32_t)(nt * 8 * SDB * 2) + 32 * kc);
            LDSM_X2(bl, b_addr_l + (uint32_t)(nt * 8 * SDB * 2) + 32 * kc);
            MMA_BF16(acc[nt], ah, bh);
            MMA_BF16(acc[nt], ah, bl);
            MMA_BF16(acc[nt], al, bh);
        }
    }

    // ---- epilogue: leaky + write Z ----
    // acc[nt]: c0,c1 -> row lane/4, cols nt*8+2*(lane%4)(+1); c2,c3 -> row+8
    {
        const int o = (lane & 3);       // within n-tile: o2 = nt*8 + 2o (+1)
        const int r0 = f0 + m0 + (lane >> 2);
        float* zp0 = g_Z + zoff + ((size_t)r0 * bins + k) * 64;
        float* zp1 = g_Z + zoff + ((size_t)(r0 + 8) * bins + k) * 64;
#pragma unroll
        for (int nt = 0; nt < 8; nt++) {
            int oo = nt * 4 + o;        // o index (0..31)
            zp0[oo]      = lk(acc[nt][0]);
            zp0[32 + oo] = lk(acc[nt][1]);
            zp1[oo]      = lk(acc[nt][2]);
            zp1[32 + oo] = lk(acc[nt][3]);
        }
    }
}

// ---------------- stage 3: irfft + bias (scalar, unchanged) ----------------
template <int N, int FPC, int COFF, int ZOFF, int OOFF>
__launch_bounds__(256)
__global__ void k_stage3(float* __restrict__ out, const float* __restrict__ bias) {
    constexpr int BINS = N / 2 + 1;
    constexpr int R = 2 * BINS;
    constexpr int SD = N + 4;
    constexpr int TPF = 256 / FPC;
    extern __shared__ float sm[];
    float* C_s = sm;
    float* Z_s = sm + N * SD;
    const int tid = threadIdx.x;

    for (int idx = tid; idx < N * N; idx += 256) {
        int t = idx / N, jj = idx % N;
        int ja = jj + (jj > 0);
        C_s[t * SD + jj] = g_C[COFF + t * R + ja];
    }
    const int f0 = blockIdx.x * FPC;
    const float4* Zg = reinterpret_cast<const float4*>(g_Z + ZOFF + (size_t)f0 * BINS * 64);
    float4* Z4 = reinterpret_cast<float4*>(Z_s);
    for (int idx = tid; idx < FPC * BINS * 16; idx += 256) Z4[idx] = Zg[idx];
    __syncthreads();

    const int fl = tid / TPF;
    const int tf = tid % TPF;
    const int txc = tf & 7;
    const int tyr = tf >> 3;

    const float4 bv = *reinterpret_cast<const float4*>(bias + OOFF + 4 * txc);
    float4 acc[4];
#pragma unroll
    for (int i = 0; i < 4; i++) acc[i] = bv;

    const float* Zf = Z_s + fl * (R * 32);

#pragma unroll 2
    for (int jc = 0; jc < N; jc += 4) {
        float4 a[4];
#pragma unroll
        for (int i = 0; i < 4; i++)
            a[i] = *reinterpret_cast<const float4*>(&C_s[(tyr * 4 + i) * SD + jc]);
        float4 b[4];
#pragma unroll
        for (int jj = 0; jj < 4; jj++) {
            int ja = jc + jj + ((jc + jj) > 0);
            b[jj] = *reinterpret_cast<const float4*>(&Zf[ja * 32 + 4 * txc]);
        }
#pragma unroll
        for (int i = 0; i < 4; i++) {
            FMA4(acc[i], a[i].x, b[0]); FMA4(acc[i], a[i].y, b[1]);
            FMA4(acc[i], a[i].z, b[2]); FMA4(acc[i], a[i].w, b[3]);
        }
    }

    const int f = f0 + fl;
#pragma unroll
    for (int i = 0; i < 4; i++) {
        int t = tyr * 4 + i;
        *reinterpret_cast<float4*>(out + ((size_t)f * N + t) * 96 + OOFF + 4 * txc) = acc[i];
    }
}

// ---------------- launch ----------------
extern "C" void kernel_launch(void* const* d_in, const int* in_sizes, int n_in,
                              void* d_out, int out_size) {
    const float* x    = (const float*)d_in[0];
    const float* kr   = (const float*)d_in[1];
    const float* ki   = (const float*)d_in[2];
    const float* bias = (const float*)d_in[3];
    float* out = (float*)d_out;

    const int s1_32  = (32 * 36 + 32 * 64) * 4;
    const int s1_64  = (64 * 68 + 64 * 64) * 4;
    const int s1_128 = (64 * 132 + 128 * 64) * 4;
    const int s2     = (128 * 136 * 2 + 64 * 136 * 2) * 2;   // 104448
    const int s3_32  = (32 * 36 + 4 * 34 * 32) * 4;
    const int s3_64  = (64 * 68 + 2 * 66 * 32) * 4;
    const int s3_128 = (128 * 132 + 130 * 32) * 4;

    cudaFuncSetAttribute(k_stage1<128, 4, 5312, 8781824, 512>,
                         cudaFuncAttributeMaxDynamicSharedMemorySize, s1_128);
    cudaFuncSetAttribute(k_stage2_tc, cudaFuncAttributeMaxDynamicSharedMemorySize, s2);
    cudaFuncSetAttribute(k_stage3<128, 1, 5312, 4390912, 64>,
                         cudaFuncAttributeMaxDynamicSharedMemorySize, s3_128);

    k_build_dft<<<dim3(65, 3), 256>>>();
    k_build_G<<<dim3(520, 3), 256>>>(kr, ki);

    k_stage1<32, 2, 0, 0, 2048><<<2048, 256, s1_32>>>(x);
    k_stage1<64, 4, 1088, 4456448, 1024><<<1024, 256, s1_64>>>(x);
    k_stage1<128, 4, 5312, 8781824, 512><<<dim3(512, 2), 256, s1_128>>>(x);

    k_stage2_tc<<<dim3(16, 17), 256, s2>>>(0, 0, 0, 2048, 17);
    k_stage2_tc<<<dim3(8, 33), 256, s2>>>(4456448, 139264, 2228224, 1024, 33);
    k_stage2_tc<<<dim3(4, 65), 256, s2>>>(8781824, 409600, 4390912, 512, 65);

    k_stage3<32, 4, 0, 0, 0><<<512, 256, s3_32>>>(out, bias);
    k_stage3<64, 2, 1088, 2228224, 32><<<512, 256, s3_64>>>(out, bias);
    k_stage3<128, 1, 5312, 4390912, 64><<<512, 256, s3_128>>>(out, bias);
}

// round 11
// speedup vs baseline: 2.9685x; 1.5000x over previous
#include <cuda_runtime.h>
#include <cuda_bf16.h>
#include <math.h>
#include <cstdint>

#define CIN 64
#define COUT_PER 32
#define LALPHA 0.2f

__device__ __forceinline__ float lk(float v) { return v > 0.f ? v : LALPHA * v; }

__device__ __forceinline__ uint32_t smem_u32(const void* p) {
    uint32_t a;
    asm("{ .reg .u64 t; cvta.to.shared.u64 t, %1; cvt.u32.u64 %0, t; }" : "=r"(a) : "l"(p));
    return a;
}
__device__ __forceinline__ uint32_t pkbf(float x, float y) {
    __nv_bfloat162 h = __floats2bfloat162_rn(x, y);
    return *reinterpret_cast<uint32_t*>(&h);
}
#define LDSM_X4(R, ADDR) \
    asm volatile("ldmatrix.sync.aligned.m8n8.x4.shared.b16 {%0,%1,%2,%3}, [%4];" \
        : "=r"((R)[0]), "=r"((R)[1]), "=r"((R)[2]), "=r"((R)[3]) : "r"(ADDR))
#define LDSM_X2(R, ADDR) \
    asm volatile("ldmatrix.sync.aligned.m8n8.x2.shared.b16 {%0,%1}, [%2];" \
        : "=r"((R)[0]), "=r"((R)[1]) : "r"(ADDR))
#define LDSM_X2_T(R, ADDR) \
    asm volatile("ldmatrix.sync.aligned.m8n8.x2.trans.shared.b16 {%0,%1}, [%2];" \
        : "=r"((R)[0]), "=r"((R)[1]) : "r"(ADDR))
#define MMA_BF16(ACC, A, B) \
    asm volatile("mma.sync.aligned.m16n8k16.row.col.f32.bf16.bf16.f32 " \
        "{%0,%1,%2,%3}, {%4,%5,%6,%7}, {%8,%9}, {%0,%1,%2,%3};" \
        : "+f"((ACC)[0]), "+f"((ACC)[1]), "+f"((ACC)[2]), "+f"((ACC)[3]) \
        : "r"((A)[0]), "r"((A)[1]), "r"((A)[2]), "r"((A)[3]), "r"((B)[0]), "r"((B)[1]))

// ---------------- static device scratch ----------------
// compact (zero-rows/cols removed) bf16 hi/lo DFT tables; elem offs: fft32->0, fft64->1024, fft128->5120
__device__ __align__(16) __nv_bfloat16 g_Dh[21504];
__device__ __align__(16) __nv_bfloat16 g_Dl[21504];
__device__ __align__(16) __nv_bfloat16 g_Ch[21504];
__device__ __align__(16) __nv_bfloat16 g_Cl[21504];
// GT[k][o2(64)][j(128)] fp32 (K-major = B col-major for mma); offs 0 / 139264 / 409600
__device__ float g_G[942080];
// X[k][f][ri][c]; offs 0 / 4456448 / 8781824
__device__ float g_X[13041664];
// Z[f][j=2k+ri][o]; offs 0 / 2228224 / 4390912
__device__ float g_Z[6520832];

// ---------------- precompute: compact bf16-split DFT tables ----------------
__global__ void k_build_dft() {
    int ffti = blockIdx.y;
    int N = 32 << ffti;
    int bins = N / 2 + 1;
    int off = (ffti == 0) ? 0 : (ffti == 1 ? 1024 : 5120);
    int total = N * N;
    int stride = gridDim.x * blockDim.x;
    for (int idx = blockIdx.x * blockDim.x + threadIdx.x; idx < total; idx += stride) {
        {   // D compact [rp][t], rp -> actual row ra = rp + (rp>0)
            int rp = idx / N, t = idx % N;
            int ra = rp + (rp > 0);
            int k = ra >> 1, ri = ra & 1;
            int m = (k * t) % N;
            float s, c;
            sincospif(2.0f * (float)m / (float)N, &s, &c);
            float v = ri ? -s : c;
            __nv_bfloat16 h = __float2bfloat16(v);
            g_Dh[off + idx] = h;
            g_Dl[off + idx] = __float2bfloat16(v - __bfloat162float(h));
        }
        {   // C compact [t][jj], jj -> actual col ja = jj + (jj>0)
            int t = idx / N, jj = idx % N;
            int ja = jj + (jj > 0);
            int k = ja >> 1, ri = ja & 1;
            int m = (k * t) % N;
            float s, c;
            sincospif(2.0f * (float)m / (float)N, &s, &c);
            float w = (k == 0 || k == bins - 1) ? 1.0f : 2.0f;
            float v = (ri ? -s : c) * (w / (float)N);
            __nv_bfloat16 h = __float2bfloat16(v);
            g_Ch[off + idx] = h;
            g_Cl[off + idx] = __float2bfloat16(v - __bfloat162float(h));
        }
    }
}

// GT[o2][j]: GT[2o][c]=vr, GT[2o+1][c]=vi, GT[2o][64+c]=-vi, GT[2o+1][64+c]=vr
__global__ void k_build_G(const float* __restrict__ kr, const float* __restrict__ ki) {
    int ffti = blockIdx.y;
    int N = 32 << ffti;
    int bins = N / 2 + 1;
    int goff = (ffti == 0) ? 0 : (ffti == 1 ? 139264 : 409600);
    int total = bins * CIN * COUT_PER;
    int stride = gridDim.x * blockDim.x;
    for (int idx = blockIdx.x * blockDim.x + threadIdx.x; idx < total; idx += stride) {
        int k = idx / (CIN * COUT_PER);
        int rem = idx % (CIN * COUT_PER);
        int c = rem / COUT_PER, o = rem % COUT_PER;
        float vr, vi;
        if (bins == 33) {
            vr = kr[k * 2048 + rem];
            vi = ki[k * 2048 + rem];
        } else {
            float src = (k + 0.5f) * (33.0f / (float)bins) - 0.5f;
            float fl = floorf(src);
            int i0 = (int)fl;
            float f = src - fl;
            int i0c = i0 < 0 ? 0 : i0;
            int i1c = i0 + 1 > 32 ? 32 : i0 + 1;
            vr = (1.0f - f) * kr[i0c * 2048 + rem] + f * kr[i1c * 2048 + rem];
            vi = (1.0f - f) * ki[i0c * 2048 + rem] + f * ki[i1c * 2048 + rem];
        }
        float* Gk = g_G + goff + k * 8192;
        Gk[(2 * o) * 128 + c]          = vr;
        Gk[(2 * o + 1) * 128 + c]      = vi;
        Gk[(2 * o) * 128 + 64 + c]     = -vi;
        Gk[(2 * o + 1) * 128 + 64 + c] = vr;
    }
}

// ---------------- stage 1: forward DFT via mma.sync ----------------
// X_out[rp rows, 64 ch] = D_compact[N x N] @ xframe[N x 64] (bf16 split, 3 passes)
template <int N, int DOFF, int XOFF, int F>
__launch_bounds__(256)
__global__ void k_stage1_tc(const float* __restrict__ x) {
    constexpr int RG = N / 16;         // row groups (1 per warp)
    constexpr int FR = 128 / N;        // frames per CTA
    constexpr int SDD = N + 8;         // D smem stride (b16)
    constexpr int SDX = 72;            // x smem stride (b16)
    extern __shared__ char smem[];
    __nv_bfloat16* Dh = reinterpret_cast<__nv_bfloat16*>(smem);
    __nv_bfloat16* Dl = Dh + N * SDD;
    __nv_bfloat16* Xh = Dl + N * SDD;
    __nv_bfloat16* Xl = Xh + 128 * SDX;

    const int tid = threadIdx.x;
    const int warp = tid >> 5, lane = tid & 31;
    const int f0 = blockIdx.x * FR;

    // copy compact bf16 D tables into strided smem
    const uint4* DhG = reinterpret_cast<const uint4*>(g_Dh + DOFF);
    const uint4* DlG = reinterpret_cast<const uint4*>(g_Dl + DOFF);
    for (int idx = tid; idx < N * N / 8; idx += 256) {
        int e = idx * 8;
        int row = e / N, col = e % N;
        *reinterpret_cast<uint4*>(&Dh[row * SDD + col]) = DhG[idx];
        *reinterpret_cast<uint4*>(&Dl[row * SDD + col]) = DlG[idx];
    }
    // load + split x frames ([t][c] layout, FR*N = 128 rows)
    const float4* xg = reinterpret_cast<const float4*>(x + (size_t)f0 * N * 64);
    for (int idx = tid; idx < 2048; idx += 256) {
        int row = idx >> 4, q = idx & 15;
        float4 v = xg[idx];
        float hx = __bfloat162float(__float2bfloat16(v.x));
        float hy = __bfloat162float(__float2bfloat16(v.y));
        float hz = __bfloat162float(__float2bfloat16(v.z));
        float hw = __bfloat162float(__float2bfloat16(v.w));
        *reinterpret_cast<uint2*>(&Xh[row * SDX + 4 * q]) =
            make_uint2(pkbf(v.x, v.y), pkbf(v.z, v.w));
        *reinterpret_cast<uint2*>(&Xl[row * SDX + 4 * q]) =
            make_uint2(pkbf(v.x - hx, v.y - hy), pkbf(v.z - hz, v.w - hw));
    }
    __syncthreads();

    const int fr = warp / RG, rg = warp % RG;
    const int m0 = rg * 16;

    float acc[8][4];
#pragma unroll
    for (int nt = 0; nt < 8; nt++)
#pragma unroll
        for (int q = 0; q < 4; q++) acc[nt][q] = 0.f;

    const uint32_t aH = smem_u32(Dh) + 2u * ((m0 + (lane & 15)) * SDD + ((lane >> 4) << 3));
    const uint32_t aL = aH + 2u * N * SDD;
    const uint32_t bH = smem_u32(Xh) + 2u * ((fr * N + (lane & 15)) * SDX);
    const uint32_t bL = bH + 2u * 128 * SDX;

#pragma unroll
    for (int kc = 0; kc < N / 16; kc++) {
        uint32_t ah[4], al[4];
        LDSM_X4(ah, aH + kc * 32);
        LDSM_X4(al, aL + kc * 32);
#pragma unroll
        for (int nt = 0; nt < 8; nt++) {
            uint32_t bh[2], bl[2];
            LDSM_X2_T(bh, bH + (uint32_t)(kc * 32 * SDX) + nt * 16);
            LDSM_X2_T(bl, bL + (uint32_t)(kc * 32 * SDX) + nt * 16);
            MMA_BF16(acc[nt], ah, bh);
            MMA_BF16(acc[nt], ah, bl);
            MMA_BF16(acc[nt], al, bh);
        }
    }

    // epilogue: write X[k][f][ri][c]
    {
        const int f = f0 + fr;
        const int rp0 = m0 + (lane >> 2);
        const int c0 = 2 * (lane & 3);
#pragma unroll
        for (int nt = 0; nt < 8; nt++) {
            int c = nt * 8 + c0;
            {
                int ra = rp0 + (rp0 > 0);
                int k = ra >> 1, ri = ra & 1;
                *reinterpret_cast<float2*>(
                    g_X + XOFF + ((size_t)(k * F + f) * 2 + ri) * 64 + c) =
                    make_float2(acc[nt][0], acc[nt][1]);
            }
            {
                int rp = rp0 + 8;
                int ra = rp + (rp > 0);
                int k = ra >> 1, ri = ra & 1;
                *reinterpret_cast<float2*>(
                    g_X + XOFF + ((size_t)(k * F + f) * 2 + ri) * 64 + c) =
                    make_float2(acc[nt][2], acc[nt][3]);
            }
        }
    }

    // zero rows: (k=0, ri=1) and (k=N/2, ri=1) per frame
    if (tid < FR * 32) {
        int fr2 = tid >> 5, m = tid & 31;
        int kz = (m >> 4) ? (N / 2) : 0;
        int q = m & 15;
        *reinterpret_cast<float4*>(
            g_X + XOFF + ((size_t)(kz * F + f0 + fr2) * 2 + 1) * 64 + 4 * q) =
            make_float4(0.f, 0.f, 0.f, 0.f);
    }
}

// ---------------- stage 2: mma.sync bf16-split (unchanged from R9) ----------------
__launch_bounds__(256)
__global__ void k_stage2_tc(int xoff, int goff, int zoff, int F, int bins) {
    constexpr int SDB = 136;
    extern __shared__ char smem[];
    __nv_bfloat16* Ah = reinterpret_cast<__nv_bfloat16*>(smem);
    __nv_bfloat16* Al = Ah + 128 * SDB;
    __nv_bfloat16* Bh = Al + 128 * SDB;
    __nv_bfloat16* Bl = Bh + 64 * SDB;

    const int tid = threadIdx.x;
    const int warp = tid >> 5, lane = tid & 31;
    const int k = blockIdx.y;
    const int f0 = blockIdx.x * 128;

    const float4* Xg = reinterpret_cast<const float4*>(g_X + xoff + ((size_t)k * F + f0) * 128);
    for (int idx = tid; idx < 128 * 32; idx += 256) {
        int row = idx >> 5, q = idx & 31;
        float4 v = Xg[idx];
        float hx = __bfloat162float(__float2bfloat16(v.x));
        float hy = __bfloat162float(__float2bfloat16(v.y));
        float hz = __bfloat162float(__float2bfloat16(v.z));
        float hw = __bfloat162float(__float2bfloat16(v.w));
        *reinterpret_cast<uint2*>(&Ah[row * SDB + 4 * q]) =
            make_uint2(pkbf(v.x, v.y), pkbf(v.z, v.w));
        *reinterpret_cast<uint2*>(&Al[row * SDB + 4 * q]) =
            make_uint2(pkbf(v.x - hx, v.y - hy), pkbf(v.z - hz, v.w - hw));
    }
    const float4* Gg = reinterpret_cast<const float4*>(g_G + goff + (size_t)k * 8192);
    for (int idx = tid; idx < 64 * 32; idx += 256) {
        int row = idx >> 5, q = idx & 31;
        float4 v = Gg[idx];
        float hx = __bfloat162float(__float2bfloat16(v.x));
        float hy = __bfloat162float(__float2bfloat16(v.y));
        float hz = __bfloat162float(__float2bfloat16(v.z));
        float hw = __bfloat162float(__float2bfloat16(v.w));
        *reinterpret_cast<uint2*>(&Bh[row * SDB + 4 * q]) =
            make_uint2(pkbf(v.x, v.y), pkbf(v.z, v.w));
        *reinterpret_cast<uint2*>(&Bl[row * SDB + 4 * q]) =
            make_uint2(pkbf(v.x - hx, v.y - hy), pkbf(v.z - hz, v.w - hw));
    }
    __syncthreads();

    const int m0 = warp * 16;
    float acc[8][4];
#pragma unroll
    for (int nt = 0; nt < 8; nt++)
#pragma unroll
        for (int q = 0; q < 4; q++) acc[nt][q] = 0.f;

    const uint32_t aoff = (uint32_t)((m0 + (lane & 15)) * SDB + ((lane >> 4) << 3));
    const uint32_t a_addr_h = smem_u32(Ah) + 2 * aoff;
    const uint32_t a_addr_l = smem_u32(Al) + 2 * aoff;
    const uint32_t boff = (uint32_t)((lane & 7) * SDB + (((lane >> 3) & 1) << 3));
    const uint32_t b_addr_h = smem_u32(Bh) + 2 * boff;
    const uint32_t b_addr_l = smem_u32(Bl) + 2 * boff;

#pragma unroll
    for (int kc = 0; kc < 8; kc++) {
        uint32_t ah[4], al[4];
        LDSM_X4(ah, a_addr_h + 32 * kc);
        LDSM_X4(al, a_addr_l + 32 * kc);
#pragma unroll
        for (int nt = 0; nt < 8; nt++) {
            uint32_t bh[2], bl[2];
            LDSM_X2(bh, b_addr_h + (uint32_t)(nt * 8 * SDB * 2) + 32 * kc);
            LDSM_X2(bl, b_addr_l + (uint32_t)(nt * 8 * SDB * 2) + 32 * kc);
            MMA_BF16(acc[nt], ah, bh);
            MMA_BF16(acc[nt], ah, bl);
            MMA_BF16(acc[nt], al, bh);
        }
    }

    {
        const int o = (lane & 3);
        const int r0 = f0 + m0 + (lane >> 2);
        float* zp0 = g_Z + zoff + ((size_t)r0 * bins + k) * 64;
        float* zp1 = g_Z + zoff + ((size_t)(r0 + 8) * bins + k) * 64;
#pragma unroll
        for (int nt = 0; nt < 8; nt++) {
            int oo = nt * 4 + o;
            zp0[oo]      = lk(acc[nt][0]);
            zp0[32 + oo] = lk(acc[nt][1]);
            zp1[oo]      = lk(acc[nt][2]);
            zp1[32 + oo] = lk(acc[nt][3]);
        }
    }
}

// ---------------- stage 3: irfft + bias via mma.sync ----------------
// out[t, 32 o] = C_compact[N x N] @ Z_compact[N x 32] + bias
template <int N, int COFF, int ZOFF, int OOFF>
__launch_bounds__(256)
__global__ void k_stage3_tc(float* __restrict__ out, const float* __restrict__ bias) {
    constexpr int BINS = N / 2 + 1;
    constexpr int RG = N / 16;
    constexpr int FR = 128 / N;
    constexpr int SDD = N + 8;
    constexpr int SDZ = 40;
    extern __shared__ char smem[];
    __nv_bfloat16* Ch = reinterpret_cast<__nv_bfloat16*>(smem);
    __nv_bfloat16* Cl = Ch + N * SDD;
    __nv_bfloat16* Zh = Cl + N * SDD;
    __nv_bfloat16* Zl = Zh + 128 * SDZ;

    const int tid = threadIdx.x;
    const int warp = tid >> 5, lane = tid & 31;
    const int f0 = blockIdx.x * FR;

    const uint4* ChG = reinterpret_cast<const uint4*>(g_Ch + COFF);
    const uint4* ClG = reinterpret_cast<const uint4*>(g_Cl + COFF);
    for (int idx = tid; idx < N * N / 8; idx += 256) {
        int e = idx * 8;
        int row = e / N, col = e % N;
        *reinterpret_cast<uint4*>(&Ch[row * SDD + col]) = ChG[idx];
        *reinterpret_cast<uint4*>(&Cl[row * SDD + col]) = ClG[idx];
    }
    // load + split Z with zero-col remap (compact row jj <- actual ja)
    for (int idx = tid; idx < 1024; idx += 256) {
        int row = idx >> 3, q = idx & 7;
        int fr = row / N, jj = row % N;
        int ja = jj + (jj > 0);
        float4 v = *reinterpret_cast<const float4*>(
            g_Z + ZOFF + (size_t)(f0 + fr) * (BINS * 64) + ja * 32 + 4 * q);
        float hx = __bfloat162float(__float2bfloat16(v.x));
        float hy = __bfloat162float(__float2bfloat16(v.y));
        float hz = __bfloat162float(__float2bfloat16(v.z));
        float hw = __bfloat162float(__float2bfloat16(v.w));
        *reinterpret_cast<uint2*>(&Zh[row * SDZ + 4 * q]) =
            make_uint2(pkbf(v.x, v.y), pkbf(v.z, v.w));
        *reinterpret_cast<uint2*>(&Zl[row * SDZ + 4 * q]) =
            make_uint2(pkbf(v.x - hx, v.y - hy), pkbf(v.z - hz, v.w - hw));
    }
    __syncthreads();

    const int fr = warp / RG, rg = warp % RG;
    const int m0 = rg * 16;

    float acc[4][4];
#pragma unroll
    for (int nt = 0; nt < 4; nt++)
#pragma unroll
        for (int q = 0; q < 4; q++) acc[nt][q] = 0.f;

    const uint32_t aH = smem_u32(Ch) + 2u * ((m0 + (lane & 15)) * SDD + ((lane >> 4) << 3));
    const uint32_t aL = aH + 2u * N * SDD;
    const uint32_t bH = smem_u32(Zh) + 2u * ((fr * N + (lane & 15)) * SDZ);
    const uint32_t bL = bH + 2u * 128 * SDZ;

#pragma unroll
    for (int kc = 0; kc < N / 16; kc++) {
        uint32_t ah[4], al[4];
        LDSM_X4(ah, aH + kc * 32);
        LDSM_X4(al, aL + kc * 32);
#pragma unroll
        for (int nt = 0; nt < 4; nt++) {
            uint32_t bh[2], bl[2];
            LDSM_X2_T(bh, bH + (uint32_t)(kc * 32 * SDZ) + nt * 16);
            LDSM_X2_T(bl, bL + (uint32_t)(kc * 32 * SDZ) + nt * 16);
            MMA_BF16(acc[nt], ah, bh);
            MMA_BF16(acc[nt], ah, bl);
            MMA_BF16(acc[nt], al, bh);
        }
    }

    // epilogue: + bias, write out[f*N+t][96] at OOFF
    {
        const int f = f0 + fr;
        const int t0 = m0 + (lane >> 2);
        const int c0 = 2 * (lane & 3);
#pragma unroll
        for (int nt = 0; nt < 4; nt++) {
            int o = nt * 8 + c0;
            float2 bv = *reinterpret_cast<const float2*>(bias + OOFF + o);
            *reinterpret_cast<float2*>(out + ((size_t)f * N + t0) * 96 + OOFF + o) =
                make_float2(acc[nt][0] + bv.x, acc[nt][1] + bv.y);
            *reinterpret_cast<float2*>(out + ((size_t)f * N + t0 + 8) * 96 + OOFF + o) =
                make_float2(acc[nt][2] + bv.x, acc[nt][3] + bv.y);
        }
    }
}

// ---------------- launch ----------------
extern "C" void kernel_launch(void* const* d_in, const int* in_sizes, int n_in,
                              void* d_out, int out_size) {
    const float* x    = (const float*)d_in[0];
    const float* kr   = (const float*)d_in[1];
    const float* ki   = (const float*)d_in[2];
    const float* bias = (const float*)d_in[3];
    float* out = (float*)d_out;

    const int s1_32  = (2 * 32 * 40 + 2 * 128 * 72) * 2;    // 41984
    const int s1_64  = (2 * 64 * 72 + 2 * 128 * 72) * 2;    // 55296
    const int s1_128 = (2 * 128 * 136 + 2 * 128 * 72) * 2;  // 106496
    const int s2     = (128 * 136 * 2 + 64 * 136 * 2) * 2;  // 104448
    const int s3_32  = (2 * 32 * 40 + 2 * 128 * 40) * 2;    // 25600
    const int s3_64  = (2 * 64 * 72 + 2 * 128 * 40) * 2;    // 38912
    const int s3_128 = (2 * 128 * 136 + 2 * 128 * 40) * 2;  // 90112

    cudaFuncSetAttribute(k_stage1_tc<64, 1024, 4456448, 1024>,
                         cudaFuncAttributeMaxDynamicSharedMemorySize, s1_64);
    cudaFuncSetAttribute(k_stage1_tc<128, 5120, 8781824, 512>,
                         cudaFuncAttributeMaxDynamicSharedMemorySize, s1_128);
    cudaFuncSetAttribute(k_stage2_tc, cudaFuncAttributeMaxDynamicSharedMemorySize, s2);
    cudaFuncSetAttribute(k_stage3_tc<128, 5120, 4390912, 64>,
                         cudaFuncAttributeMaxDynamicSharedMemorySize, s3_128);

    k_build_dft<<<dim3(64, 3), 256>>>();
    k_build_G<<<dim3(520, 3), 256>>>(kr, ki);

    k_stage1_tc<32, 0, 0, 2048><<<512, 256, s1_32>>>(x);
    k_stage1_tc<64, 1024, 4456448, 1024><<<512, 256, s1_64>>>(x);
    k_stage1_tc<128, 5120, 8781824, 512><<<512, 256, s1_128>>>(x);

    k_stage2_tc<<<dim3(16, 17), 256, s2>>>(0, 0, 0, 2048, 17);
    k_stage2_tc<<<dim3(8, 33), 256, s2>>>(4456448, 139264, 2228224, 1024, 33);
    k_stage2_tc<<<dim3(4, 65), 256, s2>>>(8781824, 409600, 4390912, 512, 65);

    k_stage3_tc<32, 0, 0, 0><<<512, 256, s3_32>>>(out, bias);
    k_stage3_tc<64, 1024, 2228224, 32><<<512, 256, s3_64>>>(out, bias);
    k_stage3_tc<128, 5120, 4390912, 64><<<512, 256, s3_128>>>(out, bias);
}